// round 12
// baseline (speedup 1.0000x reference)
#include <cuda_runtime.h>
#include <cuda_fp16.h>
#include <cstdint>

// ---------------- problem constants ----------------
constexpr int Cdim = 512;          // channels (GEMM K and N)
constexpr int Mrows = 32768;       // B*L
constexpr int BM = 64, BN = 128, BK = 32;
constexpr int KIT = Cdim / BK;     // 16 k-slabs

// ---------------- gemm smem layout ----------------
constexpr int AB_STR  = 80;                        // 64B data + 16B pad (conflict-free)
constexpr int A_STAGE = 64  * AB_STR;              // 5120
constexpr int B_STAGE = 128 * AB_STR;              // 10240
constexpr int STAGEB  = A_STAGE + B_STAGE;         // 15360
constexpr int SMEM_BYTES = 3 * STAGEB;             // 46080 -> 4 CTAs/SM

// intermediates built per launch
__device__ __half g_wpwh[Cdim * Cdim];             // fp16 w_pw
__device__ __half g_A[(size_t)Mrows * Cdim];       // fp16 dw output (32 MB, L2-hot)

// ---------------- helpers ----------------
static __device__ __forceinline__ uint32_t smem_u32(const void* p) {
    uint32_t a;
    asm("{ .reg .u64 t; cvta.to.shared.u64 t, %1; cvt.u32.u64 %0, t; }" : "=r"(a) : "l"(p));
    return a;
}
static __device__ __forceinline__ void cpa16s(uint32_t dst, const void* src) {
    asm volatile("cp.async.cg.shared.global [%0], [%1], 16;" :: "r"(dst), "l"(src));
}
static __device__ __forceinline__ void ldmx4(uint32_t* r, uint32_t a) {
    asm volatile("ldmatrix.sync.aligned.m8n8.x4.shared.b16 {%0,%1,%2,%3}, [%4];"
                 : "=r"(r[0]), "=r"(r[1]), "=r"(r[2]), "=r"(r[3]) : "r"(a));
}
static __device__ __forceinline__ void hmma(float* c, const uint32_t* a,
                                            uint32_t b0, uint32_t b1) {
    asm volatile(
        "mma.sync.aligned.m16n8k16.row.col.f32.f16.f16.f32 "
        "{%0,%1,%2,%3},{%4,%5,%6,%7},{%8,%9},{%0,%1,%2,%3};"
        : "+f"(c[0]), "+f"(c[1]), "+f"(c[2]), "+f"(c[3])
        : "r"(a[0]), "r"(a[1]), "r"(a[2]), "r"(a[3]), "r"(b0), "r"(b1));
}
#define COMMIT asm volatile("cp.async.commit_group;" ::: "memory")

// ---------------- kernel 1: depthwise conv -> fp16 A, + w_pw fp32->fp16 ----------------
__global__ void __launch_bounds__(256)
dw_k(const float* __restrict__ x,     // [B,L,C]
     const int*   __restrict__ segb,  // [B,S,2]
     const float* __restrict__ wdw,   // [C,K]
     const float* __restrict__ bdw,   // [C]
     const float4* __restrict__ wpw)  // [C,C] as float4
{
    const int tid = threadIdx.x;
    if (blockIdx.x < 256) {           // ---- w_pw conversion ----
        int i = blockIdx.x * 256 + tid;
        float4 v = wpw[i];
        __half2 h0 = __floats2half2_rn(v.x, v.y);
        __half2 h1 = __floats2half2_rn(v.z, v.w);
        uint2 u;
        u.x = *reinterpret_cast<uint32_t*>(&h0);
        u.y = *reinterpret_cast<uint32_t*>(&h1);
        *reinterpret_cast<uint2*>(g_wpwh + (size_t)i * 4) = u;
        return;
    }
    // ---- depthwise conv: 4 channels x 32 rows per thread ----
    const int c0 = (tid & 127) * 4;
    const int g0 = (blockIdx.x - 256) * 64 + (tid >> 7) * 32;
    const int l0 = g0 & 4095;

    const int* sp = segb + (g0 >> 12) * 16;
    int st[7];
    #pragma unroll
    for (int s = 0; s < 7; s++) st[s] = sp[2 * (s + 1)];

    // fast path iff every row in [l0, l0+31] has all 5 taps valid:
    // no segment start in (l0-4, l0+31], and l0 >= 4 (segment 0 starts at 0)
    bool fast = (l0 >= 4);
    #pragma unroll
    for (int s = 0; s < 7; s++)
        if (st[s] > l0 - 4 && st[s] <= l0 + 31) fast = false;

    float4 wv[5];
    #pragma unroll
    for (int j = 0; j < 5; j++) {
        wv[j].x = wdw[(c0 + 0) * 5 + j];
        wv[j].y = wdw[(c0 + 1) * 5 + j];
        wv[j].z = wdw[(c0 + 2) * 5 + j];
        wv[j].w = wdw[(c0 + 3) * 5 + j];
    }
    const float4 bv = *(const float4*)(bdw + c0);

    float4 xw[5];
    #pragma unroll
    for (int d = 0; d < 4; d++) {
        int m = g0 - 4 + d; if (m < 0) m = 0;
        xw[d] = *(const float4*)(x + (size_t)m * Cdim + c0);
    }

    if (fast) {
        // branch-free: all 5 taps, no segment logic
        #pragma unroll
        for (int r = 0; r < 32; r++) {
            const int g = g0 + r;
            xw[(r + 4) % 5] = *(const float4*)(x + (size_t)g * Cdim + c0);
            float4 a = bv;
            #pragma unroll
            for (int j = 0; j < 5; j++) {
                const float4 v = xw[(r + j) % 5];
                a.x += wv[j].x * v.x; a.y += wv[j].y * v.y;
                a.z += wv[j].z * v.z; a.w += wv[j].w * v.w;
            }
            __half2 h0 = __floats2half2_rn(a.x, a.y);
            __half2 h1 = __floats2half2_rn(a.z, a.w);
            uint2 u;
            u.x = *reinterpret_cast<uint32_t*>(&h0);
            u.y = *reinterpret_cast<uint32_t*>(&h1);
            *reinterpret_cast<uint2*>(g_A + (size_t)g * Cdim + c0) = u;
        }
    } else {
        #pragma unroll
        for (int r = 0; r < 32; r++) {
            const int g = g0 + r;
            xw[(r + 4) % 5] = *(const float4*)(x + (size_t)g * Cdim + c0);
            const int l = g & 4095;
            int ss = 0;
            #pragma unroll
            for (int s = 0; s < 7; s++)
                if (st[s] <= l && st[s] > ss) ss = st[s];
            int nt = l - ss + 1; if (nt > 5) nt = 5;

            float4 a = bv;
            const float4 x0 = xw[(r + 4) % 5];
            a.x += wv[4].x * x0.x; a.y += wv[4].y * x0.y;
            a.z += wv[4].z * x0.z; a.w += wv[4].w * x0.w;
            if (nt > 1) { const float4 v = xw[(r + 3) % 5];
                a.x += wv[3].x * v.x; a.y += wv[3].y * v.y;
                a.z += wv[3].z * v.z; a.w += wv[3].w * v.w; }
            if (nt > 2) { const float4 v = xw[(r + 2) % 5];
                a.x += wv[2].x * v.x; a.y += wv[2].y * v.y;
                a.z += wv[2].z * v.z; a.w += wv[2].w * v.w; }
            if (nt > 3) { const float4 v = xw[(r + 1) % 5];
                a.x += wv[1].x * v.x; a.y += wv[1].y * v.y;
                a.z += wv[1].z * v.z; a.w += wv[1].w * v.w; }
            if (nt > 4) { const float4 v = xw[(r + 0) % 5];
                a.x += wv[0].x * v.x; a.y += wv[0].y * v.y;
                a.z += wv[0].z * v.z; a.w += wv[0].w * v.w; }

            __half2 h0 = __floats2half2_rn(a.x, a.y);
            __half2 h1 = __floats2half2_rn(a.z, a.w);
            uint2 u;
            u.x = *reinterpret_cast<uint32_t*>(&h0);
            u.y = *reinterpret_cast<uint32_t*>(&h1);
            *reinterpret_cast<uint2*>(g_A + (size_t)g * Cdim + c0) = u;
        }
    }
}

// ---------------- kernel 2: fp16 GEMM 64x128 CTA / 4 warps of 32x64, BK=32 ----------------
// 3-stage cp.async ring + wait_group 1: two mma-stages of load cover; 4 CTAs/SM.
__global__ void __launch_bounds__(128, 4)
gemm_k(const float* __restrict__ bpw,   // [C]
       float*       __restrict__ out)   // [B,L,C]
{
    extern __shared__ char sm[];
    const uint32_t smb = smem_u32(sm);

    const int tid  = threadIdx.x;
    const int lane = tid & 31;
    const int warp = tid >> 5;
    const int wm   = (warp >> 1) * 32;   // 0 or 32
    const int wn   = (warp & 1) * 64;    // 0 or 64
    const int bx   = blockIdx.x;
    const int m0   = (bx >> 2) * BM;     // N-tile fastest: 4 CTAs share A rows via L2
    const int n0   = (bx & 3) * BN;

    // ---- hoisted loader addresses ----
    const int rowL = tid >> 2, chL = tid & 3;      // 32 rows / 4 chunks per 128 thr
    const __half* gA = g_A    + (size_t)(m0 + rowL) * Cdim + chL * 8;
    const __half* gB = g_wpwh + (size_t)(n0 + rowL) * Cdim + chL * 8;
    const uint32_t sdA = smb + rowL * AB_STR + chL * 16;              // + stage*STAGEB
    const uint32_t sdB = smb + A_STAGE + rowL * AB_STR + chL * 16;

    // ---- hoisted ldmatrix bases ----
    const uint32_t ab0 = smb + (wm + (lane & 15)) * AB_STR + (lane >> 4) * 16;
    const uint32_t bb0 = smb + A_STAGE + (wn + (lane & 7) + ((lane >> 4) & 1) * 8) * AB_STR
                       + ((lane >> 3) & 1) * 16;

    auto load_slab = [&](int s, int stage) {
        if (s >= KIT) return;
        const __half* ga = gA + s * BK;
        const __half* gb = gB + s * BK;
        const uint32_t da = sdA + stage * STAGEB;
        const uint32_t db = sdB + stage * STAGEB;
        #pragma unroll
        for (int q = 0; q < 2; q++)          // A: 64 rows x 64B
            cpa16s(da + q * 32 * AB_STR, ga + (size_t)q * 32 * Cdim);
        #pragma unroll
        for (int q = 0; q < 4; q++)          // B: 128 rows x 64B
            cpa16s(db + q * 32 * AB_STR, gb + (size_t)q * 32 * Cdim);
    };

    float cacc[2][8][4];
    #pragma unroll
    for (int i = 0; i < 2; i++)
        #pragma unroll
        for (int j = 0; j < 8; j++)
            #pragma unroll
            for (int k = 0; k < 4; k++) cacc[i][j][k] = 0.f;

    auto mma_stage = [&](int stage) {
        const uint32_t aaddr = ab0 + stage * STAGEB;
        const uint32_t baddr = bb0 + stage * STAGEB;
        #pragma unroll
        for (int ks = 0; ks < 2; ks++) {          // 2 x k16 within BK=32
            uint32_t af[2][4], bf[4][4];
            #pragma unroll
            for (int mt = 0; mt < 2; mt++)
                ldmx4(af[mt], aaddr + mt * 16 * AB_STR + ks * 32);
            #pragma unroll
            for (int g = 0; g < 4; g++)
                ldmx4(bf[g], baddr + g * 16 * AB_STR + ks * 32);
            #pragma unroll
            for (int mt = 0; mt < 2; mt++)
                #pragma unroll
                for (int nt = 0; nt < 8; nt++)
                    hmma(cacc[mt][nt], af[mt],
                         bf[nt >> 1][(nt & 1) * 2 + 0],
                         bf[nt >> 1][(nt & 1) * 2 + 1]);
        }
    };

    // prologue: 2 slabs in flight
    load_slab(0, 0); COMMIT;
    load_slab(1, 1); COMMIT;

    int ls = 2, ms = 0;                           // rotating stage indices
    #pragma unroll 1
    for (int it = 0; it < KIT; it++) {
        asm volatile("cp.async.wait_group 1;" ::: "memory");  // slab it landed
        __syncthreads();   // all warps past mma(it-1): stage ls reusable
        load_slab(it + 2, ls); COMMIT;                        // empty commit at tail
        mma_stage(ms);
        ls = (ls == 2) ? 0 : ls + 1;
        ms = (ms == 2) ? 0 : ms + 1;
    }

    // epilogue: + b_pw, coalesced float2 stores
    float2* outv = (float2*)out;
    #pragma unroll
    for (int nt = 0; nt < 8; nt++) {
        int gn = n0 + wn + nt * 8 + (lane & 3) * 2;
        float2 bp = *(const float2*)(bpw + gn);
        #pragma unroll
        for (int mt = 0; mt < 2; mt++) {
            int gm = m0 + wm + mt * 16 + (lane >> 2);
            float2 v0 = { cacc[mt][nt][0] + bp.x, cacc[mt][nt][1] + bp.y };
            float2 v1 = { cacc[mt][nt][2] + bp.x, cacc[mt][nt][3] + bp.y };
            outv[((size_t)gm * Cdim + gn) >> 1]       = v0;
            outv[(((size_t)gm + 8) * Cdim + gn) >> 1] = v1;
        }
    }
}

extern "C" void kernel_launch(void* const* d_in, const int* in_sizes, int n_in,
                              void* d_out, int out_size) {
    const float* x    = (const float*)d_in[0];
    const int*   segb = (const int*)  d_in[1];
    const float* wdw  = (const float*)d_in[2];
    const float* bdw  = (const float*)d_in[3];
    const float* wpw  = (const float*)d_in[4];
    const float* bpw  = (const float*)d_in[5];
    float* out = (float*)d_out;

    dw_k<<<256 + Mrows / 64, 256>>>(x, segb, wdw, bdw, (const float4*)wpw);

    cudaFuncSetAttribute(gemm_k,
                         cudaFuncAttributeMaxDynamicSharedMemorySize, SMEM_BYTES);
    dim3 grid((Mrows / BM) * (Cdim / BN));   // 2048 CTAs
    gemm_k<<<grid, 128, SMEM_BYTES>>>(bpw, out);
}

// round 13
// speedup vs baseline: 1.1104x; 1.1104x over previous
#include <cuda_runtime.h>
#include <cuda_fp16.h>
#include <cstdint>

// ---------------- problem constants ----------------
constexpr int Cdim = 512;          // channels (GEMM K and N)
constexpr int Mrows = 32768;       // B*L
constexpr int BM = 64, BN = 128, BK = 64;
constexpr int KIT = Cdim / BK;     // 8 k-slabs

// ---------------- gemm smem layout ----------------
constexpr int AB_STR  = 144;                       // 128B data + 16B pad (conflict-free)
constexpr int A_STAGE = 64  * AB_STR;              // 9216
constexpr int B_STAGE = 128 * AB_STR;              // 18432
constexpr int A_OFF   = 0;                         // 2 stages A
constexpr int B_OFF   = 2 * A_STAGE;               // 2 stages B
constexpr int SMEM_BYTES = B_OFF + 2 * B_STAGE;    // 55296 -> 4 CTAs/SM

// intermediates built per launch
__device__ __half g_wpwh[Cdim * Cdim];             // fp16 w_pw
__device__ __half g_A[(size_t)Mrows * Cdim];       // fp16 dw output (32 MB, L2-hot)

// ---------------- helpers ----------------
static __device__ __forceinline__ uint32_t smem_u32(const void* p) {
    uint32_t a;
    asm("{ .reg .u64 t; cvta.to.shared.u64 t, %1; cvt.u32.u64 %0, t; }" : "=r"(a) : "l"(p));
    return a;
}
static __device__ __forceinline__ void cpa16s(uint32_t dst, const void* src) {
    asm volatile("cp.async.cg.shared.global [%0], [%1], 16;" :: "r"(dst), "l"(src));
}
static __device__ __forceinline__ void ldmx4(uint32_t* r, uint32_t a) {
    asm volatile("ldmatrix.sync.aligned.m8n8.x4.shared.b16 {%0,%1,%2,%3}, [%4];"
                 : "=r"(r[0]), "=r"(r[1]), "=r"(r[2]), "=r"(r[3]) : "r"(a));
}
static __device__ __forceinline__ void hmma(float* c, const uint32_t* a,
                                            uint32_t b0, uint32_t b1) {
    asm volatile(
        "mma.sync.aligned.m16n8k16.row.col.f32.f16.f16.f32 "
        "{%0,%1,%2,%3},{%4,%5,%6,%7},{%8,%9},{%0,%1,%2,%3};"
        : "+f"(c[0]), "+f"(c[1]), "+f"(c[2]), "+f"(c[3])
        : "r"(a[0]), "r"(a[1]), "r"(a[2]), "r"(a[3]), "r"(b0), "r"(b1));
}
#define COMMIT asm volatile("cp.async.commit_group;" ::: "memory")

// ---------------- kernel 1: depthwise conv -> fp16 A, + w_pw fp32->fp16 ----------------
// blocks [0,256): convert w_pw.  blocks [256,768): dw conv, 64 rows each.
__global__ void __launch_bounds__(256)
dw_k(const float* __restrict__ x,     // [B,L,C]
     const int*   __restrict__ segb,  // [B,S,2]
     const float* __restrict__ wdw,   // [C,K]
     const float* __restrict__ bdw,   // [C]
     const float4* __restrict__ wpw)  // [C,C] as float4
{
    const int tid = threadIdx.x;
    if (blockIdx.x < 256) {           // ---- w_pw conversion ----
        int i = blockIdx.x * 256 + tid;
        float4 v = wpw[i];
        __half2 h0 = __floats2half2_rn(v.x, v.y);
        __half2 h1 = __floats2half2_rn(v.z, v.w);
        uint2 u;
        u.x = *reinterpret_cast<uint32_t*>(&h0);
        u.y = *reinterpret_cast<uint32_t*>(&h1);
        *reinterpret_cast<uint2*>(g_wpwh + (size_t)i * 4) = u;
        return;
    }
    // ---- depthwise conv: 4 channels x 32 rows per thread ----
    const int c0 = (tid & 127) * 4;
    const int g0 = (blockIdx.x - 256) * 64 + (tid >> 7) * 32;
    const int l0 = g0 & 4095;

    const int* sp = segb + (g0 >> 12) * 16;
    int st[7];
    #pragma unroll
    for (int s = 0; s < 7; s++) st[s] = sp[2 * (s + 1)];

    // fast path iff every row in [l0, l0+31] has all 5 taps valid:
    // no segment start in (l0-4, l0+31], and l0 >= 4 (segment 0 starts at 0)
    bool fast = (l0 >= 4);
    #pragma unroll
    for (int s = 0; s < 7; s++)
        if (st[s] > l0 - 4 && st[s] <= l0 + 31) fast = false;

    float4 wv[5];
    #pragma unroll
    for (int j = 0; j < 5; j++) {
        wv[j].x = wdw[(c0 + 0) * 5 + j];
        wv[j].y = wdw[(c0 + 1) * 5 + j];
        wv[j].z = wdw[(c0 + 2) * 5 + j];
        wv[j].w = wdw[(c0 + 3) * 5 + j];
    }
    const float4 bv = *(const float4*)(bdw + c0);

    float4 xw[5];
    #pragma unroll
    for (int d = 0; d < 4; d++) {
        int m = g0 - 4 + d; if (m < 0) m = 0;
        xw[d] = *(const float4*)(x + (size_t)m * Cdim + c0);
    }

    if (fast) {
        // branch-free: all 5 taps, no segment logic
        #pragma unroll
        for (int r = 0; r < 32; r++) {
            const int g = g0 + r;
            xw[(r + 4) % 5] = *(const float4*)(x + (size_t)g * Cdim + c0);
            float4 a = bv;
            #pragma unroll
            for (int j = 0; j < 5; j++) {
                const float4 v = xw[(r + j) % 5];
                a.x += wv[j].x * v.x; a.y += wv[j].y * v.y;
                a.z += wv[j].z * v.z; a.w += wv[j].w * v.w;
            }
            __half2 h0 = __floats2half2_rn(a.x, a.y);
            __half2 h1 = __floats2half2_rn(a.z, a.w);
            uint2 u;
            u.x = *reinterpret_cast<uint32_t*>(&h0);
            u.y = *reinterpret_cast<uint32_t*>(&h1);
            *reinterpret_cast<uint2*>(g_A + (size_t)g * Cdim + c0) = u;
        }
    } else {
        #pragma unroll
        for (int r = 0; r < 32; r++) {
            const int g = g0 + r;
            xw[(r + 4) % 5] = *(const float4*)(x + (size_t)g * Cdim + c0);
            const int l = g & 4095;
            int ss = 0;
            #pragma unroll
            for (int s = 0; s < 7; s++)
                if (st[s] <= l && st[s] > ss) ss = st[s];
            int nt = l - ss + 1; if (nt > 5) nt = 5;

            float4 a = bv;
            const float4 x0 = xw[(r + 4) % 5];
            a.x += wv[4].x * x0.x; a.y += wv[4].y * x0.y;
            a.z += wv[4].z * x0.z; a.w += wv[4].w * x0.w;
            if (nt > 1) { const float4 v = xw[(r + 3) % 5];
                a.x += wv[3].x * v.x; a.y += wv[3].y * v.y;
                a.z += wv[3].z * v.z; a.w += wv[3].w * v.w; }
            if (nt > 2) { const float4 v = xw[(r + 2) % 5];
                a.x += wv[2].x * v.x; a.y += wv[2].y * v.y;
                a.z += wv[2].z * v.z; a.w += wv[2].w * v.w; }
            if (nt > 3) { const float4 v = xw[(r + 1) % 5];
                a.x += wv[1].x * v.x; a.y += wv[1].y * v.y;
                a.z += wv[1].z * v.z; a.w += wv[1].w * v.w; }
            if (nt > 4) { const float4 v = xw[(r + 0) % 5];
                a.x += wv[0].x * v.x; a.y += wv[0].y * v.y;
                a.z += wv[0].z * v.z; a.w += wv[0].w * v.w; }

            __half2 h0 = __floats2half2_rn(a.x, a.y);
            __half2 h1 = __floats2half2_rn(a.z, a.w);
            uint2 u;
            u.x = *reinterpret_cast<uint32_t*>(&h0);
            u.y = *reinterpret_cast<uint32_t*>(&h1);
            *reinterpret_cast<uint2*>(g_A + (size_t)g * Cdim + c0) = u;
        }
    }
}

// ---------------- kernel 2: fp16 GEMM 64x128 CTA / 4 warps of 32x64, BK=64 ----------------
// 2-stage pipeline, 4 CTAs/SM; all hot-loop addresses hoisted (R11 config, measured 63.8us).
__global__ void __launch_bounds__(128, 4)
gemm_k(const float* __restrict__ bpw,   // [C]
       float*       __restrict__ out)   // [B,L,C]
{
    extern __shared__ char sm[];
    const uint32_t smb = smem_u32(sm);

    const int tid  = threadIdx.x;
    const int lane = tid & 31;
    const int warp = tid >> 5;
    const int wm   = (warp >> 1) * 32;   // 0 or 32
    const int wn   = (warp & 1) * 64;    // 0 or 64
    const int bx   = blockIdx.x;
    const int m0   = (bx >> 2) * BM;     // N-tile fastest: 4 CTAs share A rows via L2
    const int n0   = (bx & 3) * BN;

    // ---- hoisted loader addresses (per thread) ----
    const int rowL = tid >> 3, chL = tid & 7;
    const __half* gA = g_A    + (size_t)(m0 + rowL) * Cdim + chL * 8;
    const __half* gB = g_wpwh + (size_t)(n0 + rowL) * Cdim + chL * 8;
    const uint32_t sdA = smb + A_OFF + rowL * AB_STR + chL * 16;
    const uint32_t sdB = smb + B_OFF + rowL * AB_STR + chL * 16;

    // ---- hoisted ldmatrix bases ----
    const uint32_t ab0 = smb + A_OFF + (wm + (lane & 15)) * AB_STR + (lane >> 4) * 16;
    const uint32_t bb0 = smb + B_OFF + (wn + (lane & 7) + ((lane >> 4) & 1) * 8) * AB_STR
                       + ((lane >> 3) & 1) * 16;

    auto load_slab = [&](int s, int stage) {
        if (s >= KIT) return;
        const __half* ga = gA + s * BK;
        const __half* gb = gB + s * BK;
        const uint32_t da = sdA + stage * A_STAGE;
        const uint32_t db = sdB + stage * B_STAGE;
        #pragma unroll
        for (int q = 0; q < 4; q++)          // A: 64 rows
            cpa16s(da + q * 16 * AB_STR, ga + (size_t)q * 16 * Cdim);
        #pragma unroll
        for (int q = 0; q < 8; q++)          // B: 128 rows
            cpa16s(db + q * 16 * AB_STR, gb + (size_t)q * 16 * Cdim);
    };

    float cacc[2][8][4];
    #pragma unroll
    for (int i = 0; i < 2; i++)
        #pragma unroll
        for (int j = 0; j < 8; j++)
            #pragma unroll
            for (int k = 0; k < 4; k++) cacc[i][j][k] = 0.f;

    auto mma_stage = [&](int stage) {
        const uint32_t aaddr = ab0 + stage * A_STAGE;
        const uint32_t baddr = bb0 + stage * B_STAGE;
        #pragma unroll
        for (int ks = 0; ks < 4; ks++) {          // 4 x k16 within BK=64
            uint32_t af[2][4], bf[4][4];
            #pragma unroll
            for (int mt = 0; mt < 2; mt++)
                ldmx4(af[mt], aaddr + mt * 16 * AB_STR + ks * 32);
            #pragma unroll
            for (int g = 0; g < 4; g++)
                ldmx4(bf[g], baddr + g * 16 * AB_STR + ks * 32);
            #pragma unroll
            for (int mt = 0; mt < 2; mt++)
                #pragma unroll
                for (int nt = 0; nt < 8; nt++)
                    hmma(cacc[mt][nt], af[mt],
                         bf[nt >> 1][(nt & 1) * 2 + 0],
                         bf[nt >> 1][(nt & 1) * 2 + 1]);
        }
    };

    // prologue: 1 slab in flight
    load_slab(0, 0); COMMIT;

    #pragma unroll 2                              // folds stage bit to immediates
    for (int it = 0; it < KIT; it++) {
        asm volatile("cp.async.wait_group 0;" ::: "memory");  // slab it landed
        __syncthreads();   // all warps past mma(it-1): other stage reusable
        load_slab(it + 1, (it + 1) & 1); COMMIT;
        mma_stage(it & 1);
    }

    // epilogue: + b_pw, coalesced float2 stores
    float2* outv = (float2*)out;
    #pragma unroll
    for (int nt = 0; nt < 8; nt++) {
        int gn = n0 + wn + nt * 8 + (lane & 3) * 2;
        float2 bp = *(const float2*)(bpw + gn);
        #pragma unroll
        for (int mt = 0; mt < 2; mt++) {
            int gm = m0 + wm + mt * 16 + (lane >> 2);
            float2 v0 = { cacc[mt][nt][0] + bp.x, cacc[mt][nt][1] + bp.y };
            float2 v1 = { cacc[mt][nt][2] + bp.x, cacc[mt][nt][3] + bp.y };
            outv[((size_t)gm * Cdim + gn) >> 1]       = v0;
            outv[(((size_t)gm + 8) * Cdim + gn) >> 1] = v1;
        }
    }
}

extern "C" void kernel_launch(void* const* d_in, const int* in_sizes, int n_in,
                              void* d_out, int out_size) {
    const float* x    = (const float*)d_in[0];
    const int*   segb = (const int*)  d_in[1];
    const float* wdw  = (const float*)d_in[2];
    const float* bdw  = (const float*)d_in[3];
    const float* wpw  = (const float*)d_in[4];
    const float* bpw  = (const float*)d_in[5];
    float* out = (float*)d_out;

    dw_k<<<256 + Mrows / 64, 256>>>(x, segb, wdw, bdw, (const float4*)wpw);

    cudaFuncSetAttribute(gemm_k,
                         cudaFuncAttributeMaxDynamicSharedMemorySize, SMEM_BYTES);
    dim3 grid((Mrows / BM) * (Cdim / BN));   // 2048 CTAs
    gemm_k<<<grid, 128, SMEM_BYTES>>>(bpw, out);
}

// round 14
// speedup vs baseline: 1.1609x; 1.0455x over previous
#include <cuda_runtime.h>
#include <cuda_fp16.h>
#include <cstdint>

// ---------------- problem constants ----------------
constexpr int Cdim = 512;          // channels (GEMM K and N)
constexpr int Mrows = 32768;       // B*L
constexpr int BM = 64, BN = 128, BK = 64;
constexpr int KIT = Cdim / BK;     // 8 k-slabs

// block-role layout in the fused grid
constexpr int NCONV = 512;                         // w_pw conversion blocks
constexpr int NDW   = Mrows / 32;                  // 1024 dw blocks (32 rows each)
constexpr int NGEMM = (Mrows / BM) * (Cdim / BN);  // 2048 gemm tiles
constexpr int GRID  = NCONV + NDW + NGEMM;         // 3584

// ---------------- gemm smem layout ----------------
constexpr int AB_STR  = 144;                       // 128B data + 16B pad (conflict-free)
constexpr int A_STAGE = 64  * AB_STR;              // 9216
constexpr int B_STAGE = 128 * AB_STR;              // 18432
constexpr int A_OFF   = 0;                         // 2 stages A
constexpr int B_OFF   = 2 * A_STAGE;               // 2 stages B
constexpr int SMEM_BYTES = B_OFF + 2 * B_STAGE;    // 55296 -> 4 CTAs/SM

// intermediates + sync state
__device__ __half g_wpwh[Cdim * Cdim];             // fp16 w_pw
__device__ __half g_A[(size_t)Mrows * Cdim];       // fp16 dw output (32 MB, L2-hot)
__device__ int    g_dwflag[NDW];                   // per-32-row-block done flags
__device__ int    g_convcnt;                       // conv blocks completed

// ---------------- helpers ----------------
static __device__ __forceinline__ uint32_t smem_u32(const void* p) {
    uint32_t a;
    asm("{ .reg .u64 t; cvta.to.shared.u64 t, %1; cvt.u32.u64 %0, t; }" : "=r"(a) : "l"(p));
    return a;
}
static __device__ __forceinline__ void cpa16s(uint32_t dst, const void* src) {
    asm volatile("cp.async.cg.shared.global [%0], [%1], 16;" :: "r"(dst), "l"(src));
}
static __device__ __forceinline__ void ldmx4(uint32_t* r, uint32_t a) {
    asm volatile("ldmatrix.sync.aligned.m8n8.x4.shared.b16 {%0,%1,%2,%3}, [%4];"
                 : "=r"(r[0]), "=r"(r[1]), "=r"(r[2]), "=r"(r[3]) : "r"(a));
}
static __device__ __forceinline__ void hmma(float* c, const uint32_t* a,
                                            uint32_t b0, uint32_t b1) {
    asm volatile(
        "mma.sync.aligned.m16n8k16.row.col.f32.f16.f16.f32 "
        "{%0,%1,%2,%3},{%4,%5,%6,%7},{%8,%9},{%0,%1,%2,%3};"
        : "+f"(c[0]), "+f"(c[1]), "+f"(c[2]), "+f"(c[3])
        : "r"(a[0]), "r"(a[1]), "r"(a[2]), "r"(a[3]), "r"(b0), "r"(b1));
}
#define COMMIT asm volatile("cp.async.commit_group;" ::: "memory")

// ---------------- reset kernel (flags must be cleared every replay) ----------------
__global__ void reset_k() {
    int i = threadIdx.x;
    for (int j = i; j < NDW; j += 128) g_dwflag[j] = 0;
    if (i == 0) g_convcnt = 0;
}

// ---------------- fused kernel: conv | dw | gemm by block index ----------------
__global__ void __launch_bounds__(128, 4)
fused_k(const float*  __restrict__ x,     // [B,L,C]
        const int*    __restrict__ segb,  // [B,S,2]
        const float*  __restrict__ wdw,   // [C,K]
        const float*  __restrict__ bdw,   // [C]
        const float4* __restrict__ wpw,   // [C,C] as float4
        const float*  __restrict__ bpw,   // [C]
        float*        __restrict__ out)   // [B,L,C]
{
    const int tid = threadIdx.x;
    const int bx  = blockIdx.x;

    if (bx < NCONV) {                 // ======== role 1: w_pw fp32 -> fp16 ========
        int i = bx * 128 + tid;
        float4 v = wpw[i];
        __half2 h0 = __floats2half2_rn(v.x, v.y);
        __half2 h1 = __floats2half2_rn(v.z, v.w);
        uint2 u;
        u.x = *reinterpret_cast<uint32_t*>(&h0);
        u.y = *reinterpret_cast<uint32_t*>(&h1);
        *reinterpret_cast<uint2*>(g_wpwh + (size_t)i * 4) = u;
        __syncthreads();
        __threadfence();
        if (tid == 0) atomicAdd(&g_convcnt, 1);
        return;
    }

    if (bx < NCONV + NDW) {           // ======== role 2: depthwise conv ========
        const int b2 = bx - NCONV;            // 0..1023, rows [b2*32, b2*32+32)
        const int c0 = tid * 4;               // 128 threads x 4 channels
        const int g0 = b2 * 32;
        const int l0 = g0 & 4095;

        const int* sp = segb + (g0 >> 12) * 16;
        int st[7];
        #pragma unroll
        for (int s = 0; s < 7; s++) st[s] = sp[2 * (s + 1)];

        bool fast = (l0 >= 4);
        #pragma unroll
        for (int s = 0; s < 7; s++)
            if (st[s] > l0 - 4 && st[s] <= l0 + 31) fast = false;

        float4 wv[5];
        #pragma unroll
        for (int j = 0; j < 5; j++) {
            wv[j].x = wdw[(c0 + 0) * 5 + j];
            wv[j].y = wdw[(c0 + 1) * 5 + j];
            wv[j].z = wdw[(c0 + 2) * 5 + j];
            wv[j].w = wdw[(c0 + 3) * 5 + j];
        }
        const float4 bv = *(const float4*)(bdw + c0);

        float4 xw[5];
        #pragma unroll
        for (int d = 0; d < 4; d++) {
            int m = g0 - 4 + d; if (m < 0) m = 0;
            xw[d] = *(const float4*)(x + (size_t)m * Cdim + c0);
        }

        if (fast) {
            #pragma unroll
            for (int r = 0; r < 32; r++) {
                const int g = g0 + r;
                xw[(r + 4) % 5] = *(const float4*)(x + (size_t)g * Cdim + c0);
                float4 a = bv;
                #pragma unroll
                for (int j = 0; j < 5; j++) {
                    const float4 v = xw[(r + j) % 5];
                    a.x += wv[j].x * v.x; a.y += wv[j].y * v.y;
                    a.z += wv[j].z * v.z; a.w += wv[j].w * v.w;
                }
                __half2 h0 = __floats2half2_rn(a.x, a.y);
                __half2 h1 = __floats2half2_rn(a.z, a.w);
                uint2 u;
                u.x = *reinterpret_cast<uint32_t*>(&h0);
                u.y = *reinterpret_cast<uint32_t*>(&h1);
                *reinterpret_cast<uint2*>(g_A + (size_t)g * Cdim + c0) = u;
            }
        } else {
            #pragma unroll
            for (int r = 0; r < 32; r++) {
                const int g = g0 + r;
                xw[(r + 4) % 5] = *(const float4*)(x + (size_t)g * Cdim + c0);
                const int l = g & 4095;
                int ss = 0;
                #pragma unroll
                for (int s = 0; s < 7; s++)
                    if (st[s] <= l && st[s] > ss) ss = st[s];
                int nt = l - ss + 1; if (nt > 5) nt = 5;

                float4 a = bv;
                const float4 x0 = xw[(r + 4) % 5];
                a.x += wv[4].x * x0.x; a.y += wv[4].y * x0.y;
                a.z += wv[4].z * x0.z; a.w += wv[4].w * x0.w;
                if (nt > 1) { const float4 v = xw[(r + 3) % 5];
                    a.x += wv[3].x * v.x; a.y += wv[3].y * v.y;
                    a.z += wv[3].z * v.z; a.w += wv[3].w * v.w; }
                if (nt > 2) { const float4 v = xw[(r + 2) % 5];
                    a.x += wv[2].x * v.x; a.y += wv[2].y * v.y;
                    a.z += wv[2].z * v.z; a.w += wv[2].w * v.w; }
                if (nt > 3) { const float4 v = xw[(r + 1) % 5];
                    a.x += wv[1].x * v.x; a.y += wv[1].y * v.y;
                    a.z += wv[1].z * v.z; a.w += wv[1].w * v.w; }
                if (nt > 4) { const float4 v = xw[(r + 0) % 5];
                    a.x += wv[0].x * v.x; a.y += wv[0].y * v.y;
                    a.z += wv[0].z * v.z; a.w += wv[0].w * v.w; }

                __half2 h0 = __floats2half2_rn(a.x, a.y);
                __half2 h1 = __floats2half2_rn(a.z, a.w);
                uint2 u;
                u.x = *reinterpret_cast<uint32_t*>(&h0);
                u.y = *reinterpret_cast<uint32_t*>(&h1);
                *reinterpret_cast<uint2*>(g_A + (size_t)g * Cdim + c0) = u;
            }
        }
        __syncthreads();
        __threadfence();
        if (tid == 0) atomicExch(&g_dwflag[b2], 1);
        return;
    }

    // ======== role 3: fp16 GEMM 64x128 tile (R13 structure, flag-gated) ========
    extern __shared__ char sm[];
    const uint32_t smb = smem_u32(sm);

    const int gb   = bx - NCONV - NDW;    // 0..2047
    const int lane = tid & 31;
    const int warp = tid >> 5;
    const int wm   = (warp >> 1) * 32;    // 0 or 32
    const int wn   = (warp & 1) * 64;     // 0 or 64
    const int m0   = (gb >> 2) * BM;      // N-tile fastest: 4 CTAs share A rows via L2
    const int n0   = (gb & 3) * BN;

    // gate: wait for w_pw conversion + our two 32-row dw blocks
    if (tid == 0) {
        const int f0 = m0 >> 5;
        while (atomicAdd(&g_convcnt, 0) < NCONV)   __nanosleep(64);
        while (atomicAdd(&g_dwflag[f0], 0) == 0)   __nanosleep(64);
        while (atomicAdd(&g_dwflag[f0 + 1], 0) == 0) __nanosleep(64);
        __threadfence();
    }
    __syncthreads();

    // ---- hoisted loader addresses (per thread) ----
    const int rowL = tid >> 3, chL = tid & 7;
    const __half* gA = g_A    + (size_t)(m0 + rowL) * Cdim + chL * 8;
    const __half* gB = g_wpwh + (size_t)(n0 + rowL) * Cdim + chL * 8;
    const uint32_t sdA = smb + A_OFF + rowL * AB_STR + chL * 16;
    const uint32_t sdB = smb + B_OFF + rowL * AB_STR + chL * 16;

    // ---- hoisted ldmatrix bases ----
    const uint32_t ab0 = smb + A_OFF + (wm + (lane & 15)) * AB_STR + (lane >> 4) * 16;
    const uint32_t bb0 = smb + B_OFF + (wn + (lane & 7) + ((lane >> 4) & 1) * 8) * AB_STR
                       + ((lane >> 3) & 1) * 16;

    auto load_slab = [&](int s, int stage) {
        if (s >= KIT) return;
        const __half* ga = gA + s * BK;
        const __half* gb2 = gB + s * BK;
        const uint32_t da = sdA + stage * A_STAGE;
        const uint32_t db = sdB + stage * B_STAGE;
        #pragma unroll
        for (int q = 0; q < 4; q++)          // A: 64 rows
            cpa16s(da + q * 16 * AB_STR, ga + (size_t)q * 16 * Cdim);
        #pragma unroll
        for (int q = 0; q < 8; q++)          // B: 128 rows
            cpa16s(db + q * 16 * AB_STR, gb2 + (size_t)q * 16 * Cdim);
    };

    float cacc[2][8][4];
    #pragma unroll
    for (int i = 0; i < 2; i++)
        #pragma unroll
        for (int j = 0; j < 8; j++)
            #pragma unroll
            for (int k = 0; k < 4; k++) cacc[i][j][k] = 0.f;

    auto mma_stage = [&](int stage) {
        const uint32_t aaddr = ab0 + stage * A_STAGE;
        const uint32_t baddr = bb0 + stage * B_STAGE;
        #pragma unroll
        for (int ks = 0; ks < 4; ks++) {          // 4 x k16 within BK=64
            uint32_t af[2][4], bf[4][4];
            #pragma unroll
            for (int mt = 0; mt < 2; mt++)
                ldmx4(af[mt], aaddr + mt * 16 * AB_STR + ks * 32);
            #pragma unroll
            for (int g = 0; g < 4; g++)
                ldmx4(bf[g], baddr + g * 16 * AB_STR + ks * 32);
            #pragma unroll
            for (int mt = 0; mt < 2; mt++)
                #pragma unroll
                for (int nt = 0; nt < 8; nt++)
                    hmma(cacc[mt][nt], af[mt],
                         bf[nt >> 1][(nt & 1) * 2 + 0],
                         bf[nt >> 1][(nt & 1) * 2 + 1]);
        }
    };

    // prologue: 1 slab in flight
    load_slab(0, 0); COMMIT;

    #pragma unroll 2
    for (int it = 0; it < KIT; it++) {
        asm volatile("cp.async.wait_group 0;" ::: "memory");
        __syncthreads();
        load_slab(it + 1, (it + 1) & 1); COMMIT;
        mma_stage(it & 1);
    }

    // epilogue: + b_pw, coalesced float2 stores
    float2* outv = (float2*)out;
    #pragma unroll
    for (int nt = 0; nt < 8; nt++) {
        int gn = n0 + wn + nt * 8 + (lane & 3) * 2;
        float2 bp = *(const float2*)(bpw + gn);
        #pragma unroll
        for (int mt = 0; mt < 2; mt++) {
            int gm = m0 + wm + mt * 16 + (lane >> 2);
            float2 v0 = { cacc[mt][nt][0] + bp.x, cacc[mt][nt][1] + bp.y };
            float2 v1 = { cacc[mt][nt][2] + bp.x, cacc[mt][nt][3] + bp.y };
            outv[((size_t)gm * Cdim + gn) >> 1]       = v0;
            outv[(((size_t)gm + 8) * Cdim + gn) >> 1] = v1;
        }
    }
}

extern "C" void kernel_launch(void* const* d_in, const int* in_sizes, int n_in,
                              void* d_out, int out_size) {
    const float* x    = (const float*)d_in[0];
    const int*   segb = (const int*)  d_in[1];
    const float* wdw  = (const float*)d_in[2];
    const float* bdw  = (const float*)d_in[3];
    const float* wpw  = (const float*)d_in[4];
    const float* bpw  = (const float*)d_in[5];
    float* out = (float*)d_out;

    reset_k<<<1, 128>>>();

    cudaFuncSetAttribute(fused_k,
                         cudaFuncAttributeMaxDynamicSharedMemorySize, SMEM_BYTES);
    fused_k<<<GRID, 128, SMEM_BYTES>>>(x, segb, wdw, bdw,
                                       (const float4*)wpw, bpw, out);
}